// round 1
// baseline (speedup 1.0000x reference)
#include <cuda_runtime.h>

#define Nn 96000
#define Ee 600000
#define Bb 64
#define MLEc 1500
#define HFc 128
#define RPB 16

// ---- scratch (static device globals; no allocs allowed) ----
__device__ float g_proj[(size_t)Nn * HFc];   // 49 MB
__device__ float g_ssrc[Nn * 4];
__device__ float g_strg[Nn * 4];
__device__ float g_dsrc[Nn * 4];
__device__ float g_dtrg[Nn * 4];
__device__ float g_ew[(size_t)Ee * 4];       // 9.6 MB
__device__ float g_csrc[Bb * HFc];
__device__ float g_ctrg[Bb * HFc];
__device__ float g_M[Bb * 256];              // [b][d][h], d<64, h<4

__device__ __forceinline__ void red4(float* p, float4 v) {
    asm volatile("red.global.add.v4.f32 [%0], {%1,%2,%3,%4};"
                 :: "l"(p), "f"(v.x), "f"(v.y), "f"(v.z), "f"(v.w) : "memory");
}

// ---- kernel A: bridge coefficients + folded edge-score matrix M ----
__global__ __launch_bounds__(128) void bridge_kernel(
    const float* __restrict__ ins,
    const float* __restrict__ Wsrc, const float* __restrict__ bsrc,
    const float* __restrict__ Wtrg, const float* __restrict__ btrg,
    const float* __restrict__ Wei,  const float* __restrict__ bei,
    const float* __restrict__ asrc, const float* __restrict__ atrg,
    const float* __restrict__ aedg, const float* __restrict__ Wedge) {
    __shared__ float s_ins[256];
    __shared__ float s_ce[128];
    int b = blockIdx.x, j = threadIdx.x;
    for (int i = j; i < 256; i += 128) s_ins[i] = ins[b * 256 + i];
    __syncthreads();
    float aS = bsrc[j], aT = btrg[j], aE = bei[j];
    for (int k = 0; k < 256; k++) {
        float v = s_ins[k];
        aS += v * Wsrc[k * 128 + j];
        aT += v * Wtrg[k * 128 + j];
        aE += v * Wei[k * 128 + j];
    }
    g_csrc[b * 128 + j] = aS * asrc[j];
    g_ctrg[b * 128 + j] = aT * atrg[j];
    s_ce[j] = aE * aedg[j];
    __syncthreads();
    // M[b,d,h] = sum_f W_edge[d, h*32+f] * ce[h*32+f]
    for (int idx = j; idx < 256; idx += 128) {
        int d = idx >> 2, h = idx & 3;
        float m = 0.f;
        #pragma unroll
        for (int f = 0; f < 32; f++)
            m += Wedge[d * 128 + h * 32 + f] * s_ce[h * 32 + f];
        g_M[b * 256 + idx] = m;
    }
}

// ---- kernel B: proj + skip GEMMs, node scores, init out & denoms ----
__global__ __launch_bounds__(128) void node_kernel(
    const float* __restrict__ x, const float* __restrict__ Wp,
    const float* __restrict__ Ws, const float* __restrict__ bias,
    float* __restrict__ out) {
    __shared__ __align__(16) float xs[RPB][128];
    int j = threadIdx.x;
    int n0 = blockIdx.x * RPB;
    const float4* xg = reinterpret_cast<const float4*>(x + (size_t)n0 * 128);
    float4* xs4 = reinterpret_cast<float4*>(&xs[0][0]);
    #pragma unroll
    for (int i = 0; i < 4; i++) xs4[j + i * 128] = xg[j + i * 128];
    __syncthreads();

    float accp[RPB], accs[RPB];
    #pragma unroll
    for (int r = 0; r < RPB; r++) { accp[r] = 0.f; accs[r] = 0.f; }

    for (int k = 0; k < 128; k += 4) {
        float w1a = Wp[(k + 0) * 128 + j], w1b = Wp[(k + 1) * 128 + j];
        float w1c = Wp[(k + 2) * 128 + j], w1d = Wp[(k + 3) * 128 + j];
        float w2a = Ws[(k + 0) * 128 + j], w2b = Ws[(k + 1) * 128 + j];
        float w2c = Ws[(k + 2) * 128 + j], w2d = Ws[(k + 3) * 128 + j];
        #pragma unroll
        for (int r = 0; r < RPB; r++) {
            float4 xv = *reinterpret_cast<const float4*>(&xs[r][k]);
            accp[r] += xv.x * w1a; accp[r] += xv.y * w1b;
            accp[r] += xv.z * w1c; accp[r] += xv.w * w1d;
            accs[r] += xv.x * w2a; accs[r] += xv.y * w2b;
            accs[r] += xv.z * w2c; accs[r] += xv.w * w2d;
        }
    }

    int warp = j >> 5, lane = j & 31;
    float bj = bias[j];
    #pragma unroll
    for (int r = 0; r < RPB; r++) {
        int n = n0 + r;
        g_proj[(size_t)n * 128 + j] = accp[r];
        float sv = accs[r] + bj;
        out[(size_t)n * 256 + j] = sv;
        out[(size_t)n * 256 + 128 + j] = sv;
        int bb = n / MLEc;
        float vs = accp[r] * g_csrc[bb * 128 + j];
        float vt = accp[r] * g_ctrg[bb * 128 + j];
        #pragma unroll
        for (int o = 16; o; o >>= 1) {
            vs += __shfl_xor_sync(0xffffffffu, vs, o);
            vt += __shfl_xor_sync(0xffffffffu, vt, o);
        }
        if (lane == 0) {
            g_ssrc[n * 4 + warp] = vs;
            g_strg[n * 4 + warp] = vt;
        }
    }
    // zero denominators for this block's 16 nodes (4 heads x 2 arrays = 128)
    if (j < 64) g_dtrg[n0 * 4 + j] = 0.f;
    else        g_dsrc[n0 * 4 + (j - 64)] = 0.f;
}

// ---- kernel C: per-edge scores, exp, denominator accumulation ----
__global__ __launch_bounds__(256) void edge_kernel(
    const int* __restrict__ ei, const float* __restrict__ edges,
    const int* __restrict__ bids) {
    int gw = (blockIdx.x * 256 + threadIdx.x) >> 5;
    int lane = threadIdx.x & 31;
    if (gw >= Ee) return;
    int src = ei[gw];
    int trg = ei[Ee + gw];
    int b = bids[gw];
    float e0 = edges[(size_t)gw * 64 + lane];
    float e1 = edges[(size_t)gw * 64 + 32 + lane];
    float4 m0 = *reinterpret_cast<const float4*>(&g_M[b * 256 + lane * 4]);
    float4 m1 = *reinterpret_cast<const float4*>(&g_M[b * 256 + (lane + 32) * 4]);
    float s0 = e0 * m0.x + e1 * m1.x;
    float s1 = e0 * m0.y + e1 * m1.y;
    float s2 = e0 * m0.z + e1 * m1.z;
    float s3 = e0 * m0.w + e1 * m1.w;
    #pragma unroll
    for (int o = 16; o; o >>= 1) {
        s0 += __shfl_xor_sync(0xffffffffu, s0, o);
        s1 += __shfl_xor_sync(0xffffffffu, s1, o);
        s2 += __shfl_xor_sync(0xffffffffu, s2, o);
        s3 += __shfl_xor_sync(0xffffffffu, s3, o);
    }
    if (lane == 0) {
        float4 ss = *reinterpret_cast<const float4*>(&g_ssrc[src * 4]);
        float4 st = *reinterpret_cast<const float4*>(&g_strg[trg * 4]);
        float4 ew;
        float t;
        t = s0 + ss.x + st.x; t = (t > 0.f) ? t : 0.2f * t; ew.x = __expf(t);
        t = s1 + ss.y + st.y; t = (t > 0.f) ? t : 0.2f * t; ew.y = __expf(t);
        t = s2 + ss.z + st.z; t = (t > 0.f) ? t : 0.2f * t; ew.z = __expf(t);
        t = s3 + ss.w + st.w; t = (t > 0.f) ? t : 0.2f * t; ew.w = __expf(t);
        *reinterpret_cast<float4*>(&g_ew[(size_t)gw * 4]) = ew;
        red4(&g_dtrg[trg * 4], ew);
        red4(&g_dsrc[src * 4], ew);
    }
}

// ---- kernel C2: invert denominators ----
__global__ __launch_bounds__(256) void inv_kernel() {
    int i = blockIdx.x * 256 + threadIdx.x;
    if (i < Nn * 4) {
        g_dtrg[i] = __fdividef(1.f, g_dtrg[i] + 1e-16f);
        g_dsrc[i] = __fdividef(1.f, g_dsrc[i] + 1e-16f);
    }
}

// ---- kernel D: weighted scatter into both halves of out ----
__global__ __launch_bounds__(256) void scatter_kernel(
    const int* __restrict__ ei, float* __restrict__ out) {
    int gw = (blockIdx.x * 256 + threadIdx.x) >> 5;
    int lane = threadIdx.x & 31;
    if (gw >= Ee) return;
    int src = ei[gw];
    int trg = ei[Ee + gw];
    float4 ew = *reinterpret_cast<const float4*>(&g_ew[(size_t)gw * 4]);
    float4 it = *reinterpret_cast<const float4*>(&g_dtrg[trg * 4]);
    float4 is = *reinterpret_cast<const float4*>(&g_dsrc[src * 4]);
    int h = lane >> 3;
    float at = (h == 0) ? ew.x * it.x : (h == 1) ? ew.y * it.y
             : (h == 2) ? ew.z * it.z : ew.w * it.w;
    float as = (h == 0) ? ew.x * is.x : (h == 1) ? ew.y * is.y
             : (h == 2) ? ew.z * is.z : ew.w * is.w;
    float4 ps = *reinterpret_cast<const float4*>(&g_proj[(size_t)src * 128 + lane * 4]);
    float4 pt = *reinterpret_cast<const float4*>(&g_proj[(size_t)trg * 128 + lane * 4]);
    float4 vT = make_float4(ps.x * at, ps.y * at, ps.z * at, ps.w * at);
    float4 vS = make_float4(pt.x * as, pt.y * as, pt.z * as, pt.w * as);
    red4(&out[(size_t)trg * 256 + 128 + lane * 4], vT);  // trg_feats (cols 128..255)
    red4(&out[(size_t)src * 256 + lane * 4], vS);        // src_feats (cols 0..127)
}

// ---- kernel E: layernorm over 256 features, in place ----
__global__ __launch_bounds__(256) void ln_kernel(
    float* __restrict__ out, const float* __restrict__ gamma,
    const float* __restrict__ beta) {
    int gw = (blockIdx.x * 256 + threadIdx.x) >> 5;
    int lane = threadIdx.x & 31;
    if (gw >= Nn) return;
    float4 a  = *reinterpret_cast<const float4*>(&out[(size_t)gw * 256 + lane * 4]);
    float4 bq = *reinterpret_cast<const float4*>(&out[(size_t)gw * 256 + 128 + lane * 4]);
    float sum = a.x + a.y + a.z + a.w + bq.x + bq.y + bq.z + bq.w;
    float sq  = a.x * a.x + a.y * a.y + a.z * a.z + a.w * a.w
              + bq.x * bq.x + bq.y * bq.y + bq.z * bq.z + bq.w * bq.w;
    #pragma unroll
    for (int o = 16; o; o >>= 1) {
        sum += __shfl_xor_sync(0xffffffffu, sum, o);
        sq  += __shfl_xor_sync(0xffffffffu, sq, o);
    }
    float mu = sum * (1.f / 256.f);
    float var = sq * (1.f / 256.f) - mu * mu;
    float rs = rsqrtf(var + 1e-5f);
    float4 g1 = *reinterpret_cast<const float4*>(&gamma[lane * 4]);
    float4 g2 = *reinterpret_cast<const float4*>(&gamma[128 + lane * 4]);
    float4 b1 = *reinterpret_cast<const float4*>(&beta[lane * 4]);
    float4 b2 = *reinterpret_cast<const float4*>(&beta[128 + lane * 4]);
    a.x = (a.x - mu) * rs * g1.x + b1.x;
    a.y = (a.y - mu) * rs * g1.y + b1.y;
    a.z = (a.z - mu) * rs * g1.z + b1.z;
    a.w = (a.w - mu) * rs * g1.w + b1.w;
    bq.x = (bq.x - mu) * rs * g2.x + b2.x;
    bq.y = (bq.y - mu) * rs * g2.y + b2.y;
    bq.z = (bq.z - mu) * rs * g2.z + b2.z;
    bq.w = (bq.w - mu) * rs * g2.w + b2.w;
    *reinterpret_cast<float4*>(&out[(size_t)gw * 256 + lane * 4]) = a;
    *reinterpret_cast<float4*>(&out[(size_t)gw * 256 + 128 + lane * 4]) = bq;
}

extern "C" void kernel_launch(void* const* d_in, const int* in_sizes, int n_in,
                              void* d_out, int out_size) {
    const float* x     = (const float*)d_in[0];
    const int*   ei    = (const int*)d_in[1];
    const float* edges = (const float*)d_in[2];
    const float* ins   = (const float*)d_in[3];
    const int*   bids  = (const int*)d_in[4];
    // max_local_entity may or may not be materialized as an input tensor.
    int base = (n_in >= 21) ? 6 : 5;
    const float* Wproj = (const float*)d_in[base + 0];
    const float* Wedge = (const float*)d_in[base + 1];
    const float* Wsrc  = (const float*)d_in[base + 2];
    const float* bsrc  = (const float*)d_in[base + 3];
    const float* Wtrg  = (const float*)d_in[base + 4];
    const float* btrg  = (const float*)d_in[base + 5];
    const float* Wei   = (const float*)d_in[base + 6];
    const float* bei   = (const float*)d_in[base + 7];
    const float* asrc  = (const float*)d_in[base + 8];
    const float* atrg  = (const float*)d_in[base + 9];
    const float* aedg  = (const float*)d_in[base + 10];
    const float* bias  = (const float*)d_in[base + 11];
    const float* Wskip = (const float*)d_in[base + 12];
    const float* gamma = (const float*)d_in[base + 13];
    const float* beta  = (const float*)d_in[base + 14];
    float* out = (float*)d_out;

    bridge_kernel<<<Bb, 128>>>(ins, Wsrc, bsrc, Wtrg, btrg, Wei, bei,
                               asrc, atrg, aedg, Wedge);
    node_kernel<<<Nn / RPB, 128>>>(x, Wproj, Wskip, bias, out);
    edge_kernel<<<(Ee + 7) / 8, 256>>>(ei, edges, bids);
    inv_kernel<<<(Nn * 4 + 255) / 256, 256>>>();
    scatter_kernel<<<(Ee + 7) / 8, 256>>>(ei, out);
    ln_kernel<<<(Nn + 7) / 8, 256>>>(out, gamma, beta);
}

// round 2
// speedup vs baseline: 1.1824x; 1.1824x over previous
#include <cuda_runtime.h>
#include <cuda_bf16.h>
#include <cstdint>

#define Nn 96000
#define Ee 600000
#define Bb 64
#define MLEc 1500

#define PADA 136
#define PADB 264
#define GEMM_SMEM ((64*PADA*2 + 128*PADB*2) * 2)  // 169984 bytes

// ---- scratch ----
__device__ float g_proj[(size_t)Nn * 128];
__device__ float g_ssrc[Nn * 4];
__device__ float g_strg[Nn * 4];
__device__ float g_dsrc[Nn * 4];
__device__ float g_dtrg[Nn * 4];
__device__ float g_ew[(size_t)Ee * 4];
__device__ float g_csrc[Bb * 128];
__device__ float g_ctrg[Bb * 128];
__device__ float g_M[Bb * 256];

__device__ __forceinline__ void red4(float* p, float4 v) {
    asm volatile("red.global.add.v4.f32 [%0], {%1,%2,%3,%4};"
                 :: "l"(p), "f"(v.x), "f"(v.y), "f"(v.z), "f"(v.w) : "memory");
}
__device__ __forceinline__ uint32_t smem_u32(const void* p) {
    return (uint32_t)__cvta_generic_to_shared(p);
}
__device__ __forceinline__ void ldm_x4(uint32_t a, uint32_t& r0, uint32_t& r1,
                                       uint32_t& r2, uint32_t& r3) {
    asm volatile("ldmatrix.sync.aligned.m8n8.x4.shared.b16 {%0,%1,%2,%3},[%4];"
                 : "=r"(r0), "=r"(r1), "=r"(r2), "=r"(r3) : "r"(a));
}
__device__ __forceinline__ void ldm_x4_t(uint32_t a, uint32_t& r0, uint32_t& r1,
                                         uint32_t& r2, uint32_t& r3) {
    asm volatile("ldmatrix.sync.aligned.m8n8.x4.trans.shared.b16 {%0,%1,%2,%3},[%4];"
                 : "=r"(r0), "=r"(r1), "=r"(r2), "=r"(r3) : "r"(a));
}
__device__ __forceinline__ void mma16816(float* c, uint32_t a0, uint32_t a1,
                                         uint32_t a2, uint32_t a3,
                                         uint32_t b0, uint32_t b1) {
    asm volatile(
        "mma.sync.aligned.m16n8k16.row.col.f32.bf16.bf16.f32 "
        "{%0,%1,%2,%3},{%4,%5,%6,%7},{%8,%9},{%0,%1,%2,%3};"
        : "+f"(c[0]), "+f"(c[1]), "+f"(c[2]), "+f"(c[3])
        : "r"(a0), "r"(a1), "r"(a2), "r"(a3), "r"(b0), "r"(b1));
}
__device__ __forceinline__ void cvt_hilo(float v, __nv_bfloat16& h, __nv_bfloat16& l) {
    h = __float2bfloat16(v);
    l = __float2bfloat16(v - __bfloat162float(h));
}

// ---- kernel A: bridge coefficients + folded edge-score matrix M ----
__global__ __launch_bounds__(128) void bridge_kernel(
    const float* __restrict__ ins,
    const float* __restrict__ Wsrc, const float* __restrict__ bsrc,
    const float* __restrict__ Wtrg, const float* __restrict__ btrg,
    const float* __restrict__ Wei,  const float* __restrict__ bei,
    const float* __restrict__ asrc, const float* __restrict__ atrg,
    const float* __restrict__ aedg, const float* __restrict__ Wedge) {
    __shared__ float s_ins[256];
    __shared__ float s_ce[128];
    int b = blockIdx.x, j = threadIdx.x;
    for (int i = j; i < 256; i += 128) s_ins[i] = ins[b * 256 + i];
    __syncthreads();
    float aS = bsrc[j], aT = btrg[j], aE = bei[j];
    for (int k = 0; k < 256; k++) {
        float v = s_ins[k];
        aS += v * Wsrc[k * 128 + j];
        aT += v * Wtrg[k * 128 + j];
        aE += v * Wei[k * 128 + j];
    }
    g_csrc[b * 128 + j] = aS * asrc[j];
    g_ctrg[b * 128 + j] = aT * atrg[j];
    s_ce[j] = aE * aedg[j];
    __syncthreads();
    for (int idx = j; idx < 256; idx += 128) {
        int d = idx >> 2, h = idx & 3;
        float m = 0.f;
        #pragma unroll
        for (int f = 0; f < 32; f++)
            m += Wedge[d * 128 + h * 32 + f] * s_ce[h * 32 + f];
        g_M[b * 256 + idx] = m;
    }
}

// ---- kernel B: persistent tensor-core GEMM (proj + skip), bf16 hi/lo split ----
__global__ __launch_bounds__(512, 1) void gemm_kernel(
    const float* __restrict__ x, const float* __restrict__ Wp,
    const float* __restrict__ Ws, const float* __restrict__ bias,
    float* __restrict__ out) {
    extern __shared__ __align__(16) char smem_raw[];
    __nv_bfloat16* sAh = (__nv_bfloat16*)smem_raw;        // [64][PADA]
    __nv_bfloat16* sAl = sAh + 64 * PADA;
    __nv_bfloat16* sBh = sAl + 64 * PADA;                 // [128][PADB]
    __nv_bfloat16* sBl = sBh + 128 * PADB;

    int tid = threadIdx.x;
    int wid = tid >> 5, lane = tid & 31;
    int mw = wid >> 2, nw = wid & 3;

    // ---- convert W (proj || skip) to bf16 hi/lo once per block ----
    #pragma unroll
    for (int i = 0; i < 16; i++) {
        int e = tid + i * 512;          // float4 index, 8192 total
        int k = e >> 6, c4 = e & 63;
        float4 v4 = (c4 < 32) ? ((const float4*)Wp)[k * 32 + c4]
                              : ((const float4*)Ws)[k * 32 + (c4 - 32)];
        int col = (c4 < 32) ? c4 * 4 : 128 + (c4 - 32) * 4;
        __nv_bfloat16 h0, l0, h1, l1, h2, l2, h3, l3;
        cvt_hilo(v4.x, h0, l0); cvt_hilo(v4.y, h1, l1);
        cvt_hilo(v4.z, h2, l2); cvt_hilo(v4.w, h3, l3);
        *(__nv_bfloat162*)&sBh[k * PADB + col]     = __nv_bfloat162(h0, h1);
        *(__nv_bfloat162*)&sBh[k * PADB + col + 2] = __nv_bfloat162(h2, h3);
        *(__nv_bfloat162*)&sBl[k * PADB + col]     = __nv_bfloat162(l0, l1);
        *(__nv_bfloat162*)&sBl[k * PADB + col + 2] = __nv_bfloat162(l2, l3);
    }

    uint32_t aHiBase = smem_u32(sAh) +
        (((mw * 16 + (lane & 15)) * PADA + ((lane >> 4) << 3)) << 1);
    uint32_t aLoOff = (uint32_t)(64 * PADA) << 1;
    uint32_t bHiBase = smem_u32(sBh) +
        ((((lane & 15)) * PADB + nw * 64 + ((lane >> 4) << 3)) << 1);
    uint32_t bLoOff = (uint32_t)(128 * PADB) << 1;

    for (int tile = blockIdx.x; tile < 1500; tile += gridDim.x) {
        int n0 = tile * 64;
        __syncthreads();   // previous iteration's reads of sA done
        // ---- load + convert A tile (64 rows) ----
        #pragma unroll
        for (int i = 0; i < 4; i++) {
            int e = tid + i * 512;      // float4 index, 2048 total
            int r = e >> 5, c4 = e & 31;
            float4 v4 = ((const float4*)(x + (size_t)(n0 + r) * 128))[c4];
            int col = c4 * 4;
            __nv_bfloat16 h0, l0, h1, l1, h2, l2, h3, l3;
            cvt_hilo(v4.x, h0, l0); cvt_hilo(v4.y, h1, l1);
            cvt_hilo(v4.z, h2, l2); cvt_hilo(v4.w, h3, l3);
            *(__nv_bfloat162*)&sAh[r * PADA + col]     = __nv_bfloat162(h0, h1);
            *(__nv_bfloat162*)&sAh[r * PADA + col + 2] = __nv_bfloat162(h2, h3);
            *(__nv_bfloat162*)&sAl[r * PADA + col]     = __nv_bfloat162(l0, l1);
            *(__nv_bfloat162*)&sAl[r * PADA + col + 2] = __nv_bfloat162(l2, l3);
        }
        __syncthreads();

        float acc[8][4];
        #pragma unroll
        for (int i = 0; i < 8; i++)
            #pragma unroll
            for (int j = 0; j < 4; j++) acc[i][j] = 0.f;

        #pragma unroll
        for (int ks = 0; ks < 8; ks++) {
            int k0 = ks * 16;
            uint32_t ah0, ah1, ah2, ah3, al0, al1, al2, al3;
            ldm_x4(aHiBase + (k0 << 1), ah0, ah1, ah2, ah3);
            ldm_x4(aHiBase + aLoOff + (k0 << 1), al0, al1, al2, al3);
            #pragma unroll
            for (int nt = 0; nt < 4; nt++) {
                uint32_t addr = bHiBase + ((k0 * PADB + nt * 16) << 1);
                uint32_t bh0, bh1, bh2, bh3, bl0, bl1, bl2, bl3;
                ldm_x4_t(addr, bh0, bh1, bh2, bh3);
                ldm_x4_t(addr + bLoOff, bl0, bl1, bl2, bl3);
                mma16816(acc[nt * 2],     ah0, ah1, ah2, ah3, bh0, bh1);
                mma16816(acc[nt * 2],     ah0, ah1, ah2, ah3, bl0, bl1);
                mma16816(acc[nt * 2],     al0, al1, al2, al3, bh0, bh1);
                mma16816(acc[nt * 2 + 1], ah0, ah1, ah2, ah3, bh2, bh3);
                mma16816(acc[nt * 2 + 1], ah0, ah1, ah2, ah3, bl2, bl3);
                mma16816(acc[nt * 2 + 1], al0, al1, al2, al3, bh2, bh3);
            }
        }

        // ---- epilogue ----
        int r0 = mw * 16 + (lane >> 2);
        int n_a = n0 + r0, n_b = n0 + r0 + 8;
        #pragma unroll
        for (int nt2 = 0; nt2 < 8; nt2++) {
            int j0 = nw * 64 + nt2 * 8 + (lane & 3) * 2;
            if (j0 < 128) {
                *(float2*)&g_proj[(size_t)n_a * 128 + j0] =
                    make_float2(acc[nt2][0], acc[nt2][1]);
                *(float2*)&g_proj[(size_t)n_b * 128 + j0] =
                    make_float2(acc[nt2][2], acc[nt2][3]);
            } else {
                int jj = j0 - 128;
                float2 bv = *(const float2*)&bias[jj];
                float2 s0 = make_float2(acc[nt2][0] + bv.x, acc[nt2][1] + bv.y);
                float2 s1 = make_float2(acc[nt2][2] + bv.x, acc[nt2][3] + bv.y);
                *(float2*)&out[(size_t)n_a * 256 + jj]       = s0;
                *(float2*)&out[(size_t)n_a * 256 + 128 + jj] = s0;
                *(float2*)&out[(size_t)n_b * 256 + jj]       = s1;
                *(float2*)&out[(size_t)n_b * 256 + 128 + jj] = s1;
            }
        }
    }
}

// ---- kernel B2: per-node attention scores + denominator zeroing ----
__global__ __launch_bounds__(256) void score_kernel() {
    int gw = (blockIdx.x * 256 + threadIdx.x) >> 5;
    int lane = threadIdx.x & 31;
    if (gw >= Nn) return;
    int b = gw / MLEc;
    float4 p  = *(const float4*)&g_proj[(size_t)gw * 128 + lane * 4];
    float4 cs = *(const float4*)&g_csrc[b * 128 + lane * 4];
    float4 ct = *(const float4*)&g_ctrg[b * 128 + lane * 4];
    float vs = p.x * cs.x + p.y * cs.y + p.z * cs.z + p.w * cs.w;
    float vt = p.x * ct.x + p.y * ct.y + p.z * ct.z + p.w * ct.w;
    #pragma unroll
    for (int o = 4; o; o >>= 1) {
        vs += __shfl_xor_sync(0xffffffffu, vs, o);
        vt += __shfl_xor_sync(0xffffffffu, vt, o);
    }
    if ((lane & 7) == 0) {
        int h = lane >> 3;
        g_ssrc[gw * 4 + h] = vs;
        g_strg[gw * 4 + h] = vt;
    }
    if (lane < 4)      g_dtrg[gw * 4 + lane] = 0.f;
    else if (lane < 8) g_dsrc[gw * 4 + lane - 4] = 0.f;
}

// ---- kernel C: per-edge scores, exp, denominator accumulation ----
__global__ __launch_bounds__(256) void edge_kernel(
    const int* __restrict__ ei, const float* __restrict__ edges,
    const int* __restrict__ bids) {
    int gw = (blockIdx.x * 256 + threadIdx.x) >> 5;
    int lane = threadIdx.x & 31;
    if (gw >= Ee) return;
    int src = ei[gw];
    int trg = ei[Ee + gw];
    int b = bids[gw];
    float e0 = edges[(size_t)gw * 64 + lane];
    float e1 = edges[(size_t)gw * 64 + 32 + lane];
    float4 m0 = *reinterpret_cast<const float4*>(&g_M[b * 256 + lane * 4]);
    float4 m1 = *reinterpret_cast<const float4*>(&g_M[b * 256 + (lane + 32) * 4]);
    float s0 = e0 * m0.x + e1 * m1.x;
    float s1 = e0 * m0.y + e1 * m1.y;
    float s2 = e0 * m0.z + e1 * m1.z;
    float s3 = e0 * m0.w + e1 * m1.w;
    #pragma unroll
    for (int o = 16; o; o >>= 1) {
        s0 += __shfl_xor_sync(0xffffffffu, s0, o);
        s1 += __shfl_xor_sync(0xffffffffu, s1, o);
        s2 += __shfl_xor_sync(0xffffffffu, s2, o);
        s3 += __shfl_xor_sync(0xffffffffu, s3, o);
    }
    if (lane == 0) {
        float4 ss = *reinterpret_cast<const float4*>(&g_ssrc[src * 4]);
        float4 st = *reinterpret_cast<const float4*>(&g_strg[trg * 4]);
        float4 ew;
        float t;
        t = s0 + ss.x + st.x; t = (t > 0.f) ? t : 0.2f * t; ew.x = __expf(t);
        t = s1 + ss.y + st.y; t = (t > 0.f) ? t : 0.2f * t; ew.y = __expf(t);
        t = s2 + ss.z + st.z; t = (t > 0.f) ? t : 0.2f * t; ew.z = __expf(t);
        t = s3 + ss.w + st.w; t = (t > 0.f) ? t : 0.2f * t; ew.w = __expf(t);
        *reinterpret_cast<float4*>(&g_ew[(size_t)gw * 4]) = ew;
        red4(&g_dtrg[trg * 4], ew);
        red4(&g_dsrc[src * 4], ew);
    }
}

// ---- kernel D: weighted scatter (reciprocal folded in) ----
__global__ __launch_bounds__(256) void scatter_kernel(
    const int* __restrict__ ei, float* __restrict__ out) {
    int gw = (blockIdx.x * 256 + threadIdx.x) >> 5;
    int lane = threadIdx.x & 31;
    if (gw >= Ee) return;
    int src = ei[gw];
    int trg = ei[Ee + gw];
    float4 ew = *reinterpret_cast<const float4*>(&g_ew[(size_t)gw * 4]);
    float4 dt = *reinterpret_cast<const float4*>(&g_dtrg[trg * 4]);
    float4 ds = *reinterpret_cast<const float4*>(&g_dsrc[src * 4]);
    int h = lane >> 3;
    float ewh = (h == 0) ? ew.x : (h == 1) ? ew.y : (h == 2) ? ew.z : ew.w;
    float dth = (h == 0) ? dt.x : (h == 1) ? dt.y : (h == 2) ? dt.z : dt.w;
    float dsh = (h == 0) ? ds.x : (h == 1) ? ds.y : (h == 2) ? ds.z : ds.w;
    float at = __fdividef(ewh, dth + 1e-16f);
    float as = __fdividef(ewh, dsh + 1e-16f);
    float4 ps = *reinterpret_cast<const float4*>(&g_proj[(size_t)src * 128 + lane * 4]);
    float4 pt = *reinterpret_cast<const float4*>(&g_proj[(size_t)trg * 128 + lane * 4]);
    float4 vT = make_float4(ps.x * at, ps.y * at, ps.z * at, ps.w * at);
    float4 vS = make_float4(pt.x * as, pt.y * as, pt.z * as, pt.w * as);
    red4(&out[(size_t)trg * 256 + 128 + lane * 4], vT);
    red4(&out[(size_t)src * 256 + lane * 4], vS);
}

// ---- kernel E: layernorm over 256 features, in place ----
__global__ __launch_bounds__(256) void ln_kernel(
    float* __restrict__ out, const float* __restrict__ gamma,
    const float* __restrict__ beta) {
    int gw = (blockIdx.x * 256 + threadIdx.x) >> 5;
    int lane = threadIdx.x & 31;
    if (gw >= Nn) return;
    float4 a  = *reinterpret_cast<const float4*>(&out[(size_t)gw * 256 + lane * 4]);
    float4 bq = *reinterpret_cast<const float4*>(&out[(size_t)gw * 256 + 128 + lane * 4]);
    float sum = a.x + a.y + a.z + a.w + bq.x + bq.y + bq.z + bq.w;
    float sq  = a.x * a.x + a.y * a.y + a.z * a.z + a.w * a.w
              + bq.x * bq.x + bq.y * bq.y + bq.z * bq.z + bq.w * bq.w;
    #pragma unroll
    for (int o = 16; o; o >>= 1) {
        sum += __shfl_xor_sync(0xffffffffu, sum, o);
        sq  += __shfl_xor_sync(0xffffffffu, sq, o);
    }
    float mu = sum * (1.f / 256.f);
    float var = sq * (1.f / 256.f) - mu * mu;
    float rs = rsqrtf(var + 1e-5f);
    float4 g1 = *reinterpret_cast<const float4*>(&gamma[lane * 4]);
    float4 g2 = *reinterpret_cast<const float4*>(&gamma[128 + lane * 4]);
    float4 b1 = *reinterpret_cast<const float4*>(&beta[lane * 4]);
    float4 b2 = *reinterpret_cast<const float4*>(&beta[128 + lane * 4]);
    a.x = (a.x - mu) * rs * g1.x + b1.x;
    a.y = (a.y - mu) * rs * g1.y + b1.y;
    a.z = (a.z - mu) * rs * g1.z + b1.z;
    a.w = (a.w - mu) * rs * g1.w + b1.w;
    bq.x = (bq.x - mu) * rs * g2.x + b2.x;
    bq.y = (bq.y - mu) * rs * g2.y + b2.y;
    bq.z = (bq.z - mu) * rs * g2.z + b2.z;
    bq.w = (bq.w - mu) * rs * g2.w + b2.w;
    *reinterpret_cast<float4*>(&out[(size_t)gw * 256 + lane * 4]) = a;
    *reinterpret_cast<float4*>(&out[(size_t)gw * 256 + 128 + lane * 4]) = bq;
}

extern "C" void kernel_launch(void* const* d_in, const int* in_sizes, int n_in,
                              void* d_out, int out_size) {
    const float* x     = (const float*)d_in[0];
    const int*   ei    = (const int*)d_in[1];
    const float* edges = (const float*)d_in[2];
    const float* ins   = (const float*)d_in[3];
    const int*   bids  = (const int*)d_in[4];
    int base = (n_in >= 21) ? 6 : 5;
    const float* Wproj = (const float*)d_in[base + 0];
    const float* Wedge = (const float*)d_in[base + 1];
    const float* Wsrc  = (const float*)d_in[base + 2];
    const float* bsrc  = (const float*)d_in[base + 3];
    const float* Wtrg  = (const float*)d_in[base + 4];
    const float* btrg  = (const float*)d_in[base + 5];
    const float* Wei   = (const float*)d_in[base + 6];
    const float* bei   = (const float*)d_in[base + 7];
    const float* asrc  = (const float*)d_in[base + 8];
    const float* atrg  = (const float*)d_in[base + 9];
    const float* aedg  = (const float*)d_in[base + 10];
    const float* bias  = (const float*)d_in[base + 11];
    const float* Wskip = (const float*)d_in[base + 12];
    const float* gamma = (const float*)d_in[base + 13];
    const float* beta  = (const float*)d_in[base + 14];
    float* out = (float*)d_out;

    cudaFuncSetAttribute(gemm_kernel,
                         cudaFuncAttributeMaxDynamicSharedMemorySize, GEMM_SMEM);

    bridge_kernel<<<Bb, 128>>>(ins, Wsrc, bsrc, Wtrg, btrg, Wei, bei,
                               asrc, atrg, aedg, Wedge);
    gemm_kernel<<<148, 512, GEMM_SMEM>>>(x, Wproj, Wskip, bias, out);
    score_kernel<<<(Nn + 7) / 8, 256>>>();
    edge_kernel<<<(Ee + 7) / 8, 256>>>(ei, edges, bids);
    scatter_kernel<<<(Ee + 7) / 8, 256>>>(ei, out);
    ln_kernel<<<(Nn + 7) / 8, 256>>>(out, gamma, beta);
}